// round 4
// baseline (speedup 1.0000x reference)
#include <cuda_runtime.h>
#include <math.h>
#include <cstdint>

#define B_   4
#define N_   2048
#define D_   512
#define H_   8
#define DH   64
#define DQ2  128          // concatenated head dim: [q | q_met]
#define BHn  (B_*H_)      // 32
#define ROWS (B_*N_)      // 8192
#define SCALE 0.125f      // 64^-0.5

// Scratch (device globals — no allocations allowed)
__device__ float g_Q2[BHn * N_ * DQ2];  // 32 MB  [(bh), n, 128]  (tf32-rounded)
__device__ float g_K2[BHn * N_ * DQ2];  // 32 MB                  (tf32-rounded)
__device__ float g_Vt[BHn * DH * N_];   // 16 MB  [(bh), d, n]    (tf32-rounded, transposed)
__device__ float g_OH[ROWS * D_];       // 16 MB  (b, n, h*64+d)

// ===========================================================================
// helpers
// ===========================================================================
__device__ __forceinline__ float tf32r(float x) {
    uint32_t u = __float_as_uint(x);
    asm("cvt.rn.tf32.f32 %0, %1;" : "=r"(u) : "r"(u));
    return __uint_as_float(u);
}
__device__ __forceinline__ void mma8(float c[4], const uint32_t a[4], const uint32_t b[2]) {
    asm volatile(
        "mma.sync.aligned.m16n8k8.row.col.f32.tf32.tf32.f32 "
        "{%0,%1,%2,%3}, {%4,%5,%6,%7}, {%8,%9}, {%0,%1,%2,%3};"
        : "+f"(c[0]), "+f"(c[1]), "+f"(c[2]), "+f"(c[3])
        : "r"(a[0]), "r"(a[1]), "r"(a[2]), "r"(a[3]), "r"(b[0]), "r"(b[1]));
}

// ===========================================================================
// Kernel 1: fused projections (fp32 FMA). Epilogue rounds to tf32 + scatters
// into head-split layouts (Q2/K2 concatenated; V transposed to [d][n]).
// ===========================================================================
__global__ __launch_bounds__(256) void proj_kernel(
    const float* __restrict__ x, const float* __restrict__ met,
    const float* __restrict__ yz, const float* __restrict__ Wq,
    const float* __restrict__ Wk, const float* __restrict__ Wv)
{
    const int mode = blockIdx.z;
    const float* A = (mode == 0) ? x : (mode == 1 || mode == 3) ? met : yz;
    const float* W = (mode < 2) ? Wq : (mode < 4) ? Wk : Wv;

    __shared__ float As[16][68];
    __shared__ float Bs[16][68];

    const int tid = threadIdx.x;
    const int tx = tid % 16, ty = tid / 16;
    const int row0 = blockIdx.y * 64;
    const int col0 = blockIdx.x * 64;

    float acc[4][4] = {};

    for (int k0 = 0; k0 < D_; k0 += 16) {
        {
            int m = tid / 4, k4 = tid % 4;
            float4 v = *(const float4*)&A[(long)(row0 + m) * D_ + k0 + k4 * 4];
            As[k4*4+0][m] = v.x; As[k4*4+1][m] = v.y;
            As[k4*4+2][m] = v.z; As[k4*4+3][m] = v.w;
        }
        {
            int k = tid / 16, c4 = tid % 16;
            *(float4*)&Bs[k][c4*4] =
                *(const float4*)&W[(long)(k0 + k) * D_ + col0 + c4 * 4];
        }
        __syncthreads();
        #pragma unroll
        for (int kk = 0; kk < 16; kk++) {
            float a[4], b[4];
            *(float4*)a = *(float4*)&As[kk][ty*4];
            *(float4*)b = *(float4*)&Bs[kk][tx*4];
            #pragma unroll
            for (int i = 0; i < 4; i++)
                #pragma unroll
                for (int j = 0; j < 4; j++)
                    acc[i][j] += a[i] * b[j];
        }
        __syncthreads();
    }

    #pragma unroll
    for (int i = 0; i < 4; i++) {
        int r = row0 + ty*4 + i;
        int b = r / N_, n = r % N_;
        #pragma unroll
        for (int j = 0; j < 4; j++) {
            int c = col0 + tx*4 + j;
            int h = c / DH, d = c % DH;
            float v = tf32r(acc[i][j]);
            long base = (long)(b*H_ + h) * N_ + n;
            if      (mode == 0) g_Q2[base*DQ2 + d]      = v;
            else if (mode == 1) g_Q2[base*DQ2 + d + DH] = v;
            else if (mode == 2) g_K2[base*DQ2 + d]      = v;
            else if (mode == 3) g_K2[base*DQ2 + d + DH] = v;
            else                g_Vt[((long)(b*H_ + h)*DH + d)*N_ + n] = v;
        }
    }
}

// ===========================================================================
// Kernel 2 (FUSED): sim -> exp -> rowsum -> normalize+write attn -> PV -> OH
// CTA = (bh, 128-row strip).  8 warps: wm=wid>>1 (32 rows), wn=wid&1.
//
// Phase A: S = Q2 @ K2^T; epilogue writes p=exp(S*SCALE) unnormalized to attn,
//          accumulates per-row sums (regs -> shfl -> smem atomics).
// Phase B: re-read p chunks (L2-hot), scale by 1/rowsum, write final attn,
//          and run PV MMA on the scaled values; OH written at the end.
// ===========================================================================
#define FUSED_SMEM ((16384 + 8192 + 128) * 4)   // Qs/Pfrag + Kb/Vfrag + rowsum

__global__ __launch_bounds__(256) void attn_fused(float* __restrict__ attn)
{
    extern __shared__ uint32_t sm[];
    uint32_t* Qs = sm;               // A: Q frags [qm4][ma2][ks16][lane32][4]; B: P frags
    uint32_t* Kb = sm + 16384;       // A: K dbl buf 2x4096; B: V frags [wn2][na4][ks16][lane32][2]
    float* rowsumS = (float*)(sm + 24576);   // [128]

    const int tid = threadIdx.x, lane = tid & 31, wid = tid >> 5;
    const int wm = wid >> 1, wn = wid & 1;
    const int bh = blockIdx.y, rb = blockIdx.x;
    const float* Qg = g_Q2 + ((long)bh * N_ + rb * 128) * DQ2;
    const float* Kg = g_K2 + (long)bh * N_ * DQ2;
    const float* Vg = g_Vt + (long)bh * DH * N_;
    float* outp = attn + (long)bh * N_ * N_ + (long)rb * 128 * N_;

    // ---- Phase A ----------------------------------------------------------
    // Q resident fragment fill (once)
    for (int e = tid; e < 4096; e += 256) {
        int l = e & 31, ks = (e >> 5) & 15, ma = (e >> 9) & 1, qm = e >> 10;
        int r = qm * 32 + ma * 16 + (l >> 2), c = ks * 8 + (l & 3);
        uint4 v;
        v.x = __float_as_uint(Qg[(long)r * DQ2 + c]);
        v.y = __float_as_uint(Qg[(long)(r + 8) * DQ2 + c]);
        v.z = __float_as_uint(Qg[(long)r * DQ2 + c + 4]);
        v.w = __float_as_uint(Qg[(long)(r + 8) * DQ2 + c + 4]);
        *(uint4*)&Qs[e * 4] = v;
    }
    if (tid < 128) rowsumS[tid] = 0.f;

    float4 tmp[4];
    auto loadK = [&](int it) {
        int ct = it >> 2, kc = it & 3;
        const float* src = Kg + (long)(ct * 128) * DQ2 + kc * 32;
        #pragma unroll
        for (int q = 0; q < 4; q++) {
            int e = tid + q * 256;
            int col = e >> 3, kg = e & 7;
            tmp[q] = *(const float4*)(src + (long)col * DQ2 + kg * 4);
        }
    };
    auto storeK = [&](int buf) {
        uint32_t* Bb = Kb + buf * 4096;
        #pragma unroll
        for (int q = 0; q < 4; q++) {
            int e = tid + q * 256;
            int col = e >> 3, kg = e & 7;
            int wn_ = col >> 6, na = (col >> 3) & 7;
            uint32_t vv[4] = { __float_as_uint(tmp[q].x), __float_as_uint(tmp[q].y),
                               __float_as_uint(tmp[q].z), __float_as_uint(tmp[q].w) };
            #pragma unroll
            for (int t = 0; t < 4; t++) {
                int k = kg * 4 + t;
                int l = ((col & 7) << 2) | (k & 3);
                Bb[((((wn_ * 8 + na) * 4 + (k >> 3)) * 32) + l) * 2 + ((k >> 2) & 1)] = vv[t];
            }
        }
    };

    float rs[2][2] = {};      // per-thread row-sum partials [ma][half]
    float acc[2][8][4];
    loadK(0); storeK(0);
    __syncthreads();

    for (int it = 0; it < 64; it++) {
        const int kc = it & 3, buf = it & 1;
        if (kc == 0) {
            #pragma unroll
            for (int i = 0; i < 2; i++)
                #pragma unroll
                for (int j = 0; j < 8; j++)
                    #pragma unroll
                    for (int t = 0; t < 4; t++) acc[i][j][t] = 0.f;
        }
        if (it + 1 < 64) loadK(it + 1);

        const uint32_t* Bb = Kb + buf * 4096;
        #pragma unroll
        for (int ksl = 0; ksl < 4; ksl++) {
            int ksg = kc * 4 + ksl;
            uint32_t a[2][4], b[8][2];
            *(uint4*)a[0] = *(const uint4*)&Qs[(((wm * 2 + 0) * 16 + ksg) * 32 + lane) * 4];
            *(uint4*)a[1] = *(const uint4*)&Qs[(((wm * 2 + 1) * 16 + ksg) * 32 + lane) * 4];
            #pragma unroll
            for (int na = 0; na < 8; na++)
                *(uint2*)b[na] = *(const uint2*)&Bb[(((wn * 8 + na) * 4 + ksl) * 32 + lane) * 2];
            #pragma unroll
            for (int ma = 0; ma < 2; ma++)
                #pragma unroll
                for (int na = 0; na < 8; na++)
                    mma8(acc[ma][na], a[ma], b[na]);
        }

        if (kc == 3) {
            int ct = it >> 2;
            #pragma unroll
            for (int ma = 0; ma < 2; ma++) {
                int row = wm * 32 + ma * 16 + (lane >> 2);
                #pragma unroll
                for (int na = 0; na < 8; na++) {
                    int col = ct * 128 + wn * 64 + na * 8 + (lane & 3) * 2;
                    float p0 = __expf(acc[ma][na][0] * SCALE);
                    float p1 = __expf(acc[ma][na][1] * SCALE);
                    float p2 = __expf(acc[ma][na][2] * SCALE);
                    float p3 = __expf(acc[ma][na][3] * SCALE);
                    *(float2*)&outp[(long)row * N_ + col] = make_float2(p0, p1);
                    *(float2*)&outp[(long)(row + 8) * N_ + col] = make_float2(p2, p3);
                    rs[ma][0] += p0 + p1;
                    rs[ma][1] += p2 + p3;
                }
            }
        }
        if (it + 1 < 64) storeK(buf ^ 1);
        __syncthreads();
    }

    // row-sum reduction: shfl over the 4 lanes sharing a row, then smem atomics
    #pragma unroll
    for (int ma = 0; ma < 2; ma++)
        #pragma unroll
        for (int hf = 0; hf < 2; hf++) {
            float v = rs[ma][hf];
            v += __shfl_xor_sync(0xffffffffu, v, 1);
            v += __shfl_xor_sync(0xffffffffu, v, 2);
            if ((lane & 3) == 0)
                atomicAdd(&rowsumS[wm * 32 + ma * 16 + hf * 8 + (lane >> 2)], v);
        }
    __syncthreads();
    if (tid < 128) rowsumS[tid] = 1.0f / rowsumS[tid];
    __syncthreads();

    // ---- Phase B ----------------------------------------------------------
    // 32 half-chunks of 64 k each; alternating ks ranges [0,8) / [8,16) in the
    // frag buffers give a single __syncthreads per half-chunk.
    float pacc[2][4][4] = {};

    for (int h = 0; h < 32; h++) {
        const int ct = h >> 1, half = h & 1;
        const int cbase = ct * 128 + half * 64;

        // load P half-chunk (128 rows x 64 k), scale, write back, keep in regs
        float4 tp[8];
        #pragma unroll
        for (int q = 0; q < 8; q++) {
            int e = tid + q * 256;
            int r = e >> 4, kg = e & 15;
            float4 v = *(const float4*)&outp[(long)r * N_ + cbase + kg * 4];
            float iv = rowsumS[r];
            v.x *= iv; v.y *= iv; v.z *= iv; v.w *= iv;
            *(float4*)&outp[(long)r * N_ + cbase + kg * 4] = v;
            tp[q] = v;
        }
        // load V half-chunk (64 d x 64 k)
        float4 tv[4];
        #pragma unroll
        for (int q = 0; q < 4; q++) {
            int e = tid + q * 256;
            int d = e >> 4, kg = e & 15;
            tv[q] = *(const float4*)&Vg[(long)d * N_ + cbase + kg * 4];
        }

        // STS P frags (tf32-rounded) into Qs, ks range = half*8 ..
        #pragma unroll
        for (int q = 0; q < 8; q++) {
            int e = tid + q * 256;
            int r = e >> 4, kg = e & 15;
            int wm_ = r >> 5, ma = (r >> 4) & 1, rr = r & 15;
            float f[4] = { tp[q].x, tp[q].y, tp[q].z, tp[q].w };
            #pragma unroll
            for (int t = 0; t < 4; t++) {
                int k = kg * 4 + t;
                int ks = half * 8 + (k >> 3);
                int j = ((k >> 2) & 1) * 2 + (rr >> 3);
                int l = ((rr & 7) << 2) | (k & 3);
                Qs[((((wm_ * 2 + ma) * 16 + ks) * 32) + l) * 4 + j] =
                    __float_as_uint(tf32r(f[t]));
            }
        }
        // STS V frags into Kb
        #pragma unroll
        for (int q = 0; q < 4; q++) {
            int e = tid + q * 256;
            int d = e >> 4, kg = e & 15;
            int wn_ = d >> 5, na = (d >> 3) & 3;
            float f[4] = { tv[q].x, tv[q].y, tv[q].z, tv[q].w };
            #pragma unroll
            for (int t = 0; t < 4; t++) {
                int k = kg * 4 + t;
                int ks = half * 8 + (k >> 3);
                int l = ((d & 7) << 2) | (k & 3);
                Kb[((((wn_ * 4 + na) * 16 + ks) * 32) + l) * 2 + ((k >> 2) & 1)] =
                    __float_as_uint(f[t]);
            }
        }
        __syncthreads();

        #pragma unroll
        for (int ksl = 0; ksl < 8; ksl++) {
            int ks = half * 8 + ksl;
            uint32_t a[2][4], b[4][2];
            *(uint4*)a[0] = *(const uint4*)&Qs[(((wm * 2 + 0) * 16 + ks) * 32 + lane) * 4];
            *(uint4*)a[1] = *(const uint4*)&Qs[(((wm * 2 + 1) * 16 + ks) * 32 + lane) * 4];
            #pragma unroll
            for (int na = 0; na < 4; na++)
                *(uint2*)b[na] = *(const uint2*)&Kb[(((wn * 4 + na) * 16 + ks) * 32 + lane) * 2];
            #pragma unroll
            for (int ma = 0; ma < 2; ma++)
                #pragma unroll
                for (int na = 0; na < 4; na++)
                    mma8(pacc[ma][na], a[ma], b[na]);
        }
    }

    // OH epilogue
    const int b = bh >> 3, hh = bh & 7;
    float* oh = g_OH + ((long)b * N_ + rb * 128) * D_ + hh * DH;
    #pragma unroll
    for (int ma = 0; ma < 2; ma++) {
        int row = wm * 32 + ma * 16 + (lane >> 2);
        #pragma unroll
        for (int na = 0; na < 4; na++) {
            int col = wn * 32 + na * 8 + (lane & 3) * 2;
            *(float2*)&oh[(long)row * D_ + col] =
                make_float2(pacc[ma][na][0], pacc[ma][na][1]);
            *(float2*)&oh[(long)(row + 8) * D_ + col] =
                make_float2(pacc[ma][na][2], pacc[ma][na][3]);
        }
    }
}

// ===========================================================================
// Kernel 3: Out = OutH @ Wo + bo  (fp32)
// ===========================================================================
__global__ __launch_bounds__(256) void outproj_kernel(
    const float* __restrict__ Wo, const float* __restrict__ bo,
    float* __restrict__ out)
{
    __shared__ float As[16][68];
    __shared__ float Bs[16][68];

    const int tid = threadIdx.x;
    const int tx = tid % 16, ty = tid / 16;
    const int row0 = blockIdx.y * 64;
    const int col0 = blockIdx.x * 64;

    float acc[4][4] = {};

    for (int k0 = 0; k0 < D_; k0 += 16) {
        {
            int m = tid / 4, k4 = tid % 4;
            float4 v = *(const float4*)&g_OH[(long)(row0 + m)*D_ + k0 + k4*4];
            As[k4*4+0][m] = v.x; As[k4*4+1][m] = v.y;
            As[k4*4+2][m] = v.z; As[k4*4+3][m] = v.w;
        }
        {
            int k = tid / 16, c4 = tid % 16;
            *(float4*)&Bs[k][c4*4] =
                *(const float4*)&Wo[(long)(k0 + k)*D_ + col0 + c4*4];
        }
        __syncthreads();
        #pragma unroll
        for (int kk = 0; kk < 16; kk++) {
            float a[4], b[4];
            *(float4*)a = *(float4*)&As[kk][ty*4];
            *(float4*)b = *(float4*)&Bs[kk][tx*4];
            #pragma unroll
            for (int i = 0; i < 4; i++)
                #pragma unroll
                for (int j = 0; j < 4; j++)
                    acc[i][j] += a[i] * b[j];
        }
        __syncthreads();
    }

    #pragma unroll
    for (int i = 0; i < 4; i++) {
        int r = row0 + ty*4 + i;
        #pragma unroll
        for (int j = 0; j < 4; j++) {
            int c = col0 + tx*4 + j;
            out[(long)r * D_ + c] = acc[i][j] + bo[c];
        }
    }
}

// ===========================================================================
extern "C" void kernel_launch(void* const* d_in, const int* in_sizes, int n_in,
                              void* d_out, int out_size)
{
    (void)in_sizes; (void)n_in; (void)out_size;
    const float* x   = (const float*)d_in[0];
    const float* met = (const float*)d_in[1];
    const float* yz  = (const float*)d_in[2];
    const float* Wq  = (const float*)d_in[3];
    const float* Wk  = (const float*)d_in[4];
    const float* Wv  = (const float*)d_in[5];
    const float* Wo  = (const float*)d_in[6];
    const float* bo  = (const float*)d_in[7];

    float* out  = (float*)d_out;                       // (4, 2048, 512)
    float* attn = out + (long)B_ * N_ * D_;            // (32, 2048, 2048)

    static int configured = 0;
    if (!configured) {
        cudaFuncSetAttribute(attn_fused, cudaFuncAttributeMaxDynamicSharedMemorySize, FUSED_SMEM);
        configured = 1;
    }

    proj_kernel   <<<dim3(8, 128, 5), 256>>>(x, met, yz, Wq, Wk, Wv);
    attn_fused    <<<dim3(16, 32), 256, FUSED_SMEM>>>(attn);
    outproj_kernel<<<dim3(8, 128), 256>>>(Wo, bo, out);
}

// round 5
// speedup vs baseline: 1.5719x; 1.5719x over previous
#include <cuda_runtime.h>
#include <math.h>
#include <cstdint>

#define B_   4
#define N_   2048
#define D_   512
#define H_   8
#define DH   64
#define DQ2  128          // concatenated head dim: [q | q_met]
#define BHn  (B_*H_)      // 32
#define ROWS (B_*N_)      // 8192
#define SCALE 0.125f      // 64^-0.5

// Scratch (device globals — no allocations allowed)
__device__ float g_Q2[BHn * N_ * DQ2];  // 32 MB  [(bh), n, 128]  (tf32-rounded)
__device__ float g_K2[BHn * N_ * DQ2];  // 32 MB                  (tf32-rounded)
__device__ float g_Vt[BHn * DH * N_];   // 16 MB  [(bh), d, n]    (tf32-rounded, transposed)
__device__ float g_OH[ROWS * D_];       // 16 MB  (b, n, h*64+d)

// ===========================================================================
// helpers
// ===========================================================================
__device__ __forceinline__ float tf32r(float x) {
    uint32_t u = __float_as_uint(x);
    asm("cvt.rn.tf32.f32 %0, %1;" : "=r"(u) : "r"(u));
    return __uint_as_float(u);
}
__device__ __forceinline__ void mma8(float c[4], const uint32_t a[4], const uint32_t b[2]) {
    asm volatile(
        "mma.sync.aligned.m16n8k8.row.col.f32.tf32.tf32.f32 "
        "{%0,%1,%2,%3}, {%4,%5,%6,%7}, {%8,%9}, {%0,%1,%2,%3};"
        : "+f"(c[0]), "+f"(c[1]), "+f"(c[2]), "+f"(c[3])
        : "r"(a[0]), "r"(a[1]), "r"(a[2]), "r"(a[3]), "r"(b[0]), "r"(b[1]));
}

// ===========================================================================
// Kernel 1: proj via mma.sync tf32.  C(8192x512) = A(8192x512) @ W(512x512),
// 5 modes (blockIdx.z).  CTA tile 128x128, 8 warps (wm 0..3 x wn 0..1),
// K chunks of 32, double-buffered plain padded smem tiles:
//   A tile [128][44]  (pad 44: frag gathers + float4 STS conflict-free)
//   W tile [32][136]  (k-major; scalar transpose STS + b-frag gathers cf)
// Epilogue scatters tf32-rounded results into head-split layouts.
// ===========================================================================
#define APAD 44
#define BPAD 136
#define PROJ_SMEM ((2*128*APAD + 2*32*BPAD) * 4)   // 79872 B

__global__ __launch_bounds__(256) void proj_mma(
    const float* __restrict__ x, const float* __restrict__ met,
    const float* __restrict__ yz, const float* __restrict__ Wq,
    const float* __restrict__ Wk, const float* __restrict__ Wv)
{
    extern __shared__ float smf[];
    float* As = smf;                    // 2 x [128][APAD]
    float* Bs = smf + 2*128*APAD;       // 2 x [32][BPAD]

    const int mode = blockIdx.z;
    const float* A = (mode == 0) ? x : (mode == 1 || mode == 3) ? met : yz;
    const float* W = (mode < 2) ? Wq : (mode < 4) ? Wk : Wv;

    const int tid = threadIdx.x, lane = tid & 31, wid = tid >> 5;
    const int wm = wid >> 1, wn = wid & 1;
    const int row0 = blockIdx.y * 128;
    const int col0 = blockIdx.x * 128;

    float4 ta[4]; float tb[16];
    auto loadA = [&](int k0) {
        #pragma unroll
        for (int q = 0; q < 4; q++) {
            int e = tid + q * 256;
            int r = e >> 3, kg = e & 7;
            ta[q] = *(const float4*)&A[(long)(row0 + r) * D_ + k0 + kg * 4];
        }
    };
    auto loadB = [&](int k0) {
        #pragma unroll
        for (int j = 0; j < 16; j++) {
            int i = tid + j * 256;
            int k = i >> 7, n = i & 127;
            tb[j] = W[(long)(k0 + k) * D_ + col0 + n];
        }
    };
    auto stsA = [&](int buf) {
        float* Ab = As + buf * 128 * APAD;
        #pragma unroll
        for (int q = 0; q < 4; q++) {
            int e = tid + q * 256;
            int r = e >> 3, kg = e & 7;
            float4 v = ta[q];
            v.x = tf32r(v.x); v.y = tf32r(v.y); v.z = tf32r(v.z); v.w = tf32r(v.w);
            *(float4*)&Ab[r * APAD + kg * 4] = v;
        }
    };
    auto stsB = [&](int buf) {
        float* Bb = Bs + buf * 32 * BPAD;
        #pragma unroll
        for (int j = 0; j < 16; j++) {
            int i = tid + j * 256;
            int k = i >> 7, n = i & 127;
            Bb[k * BPAD + n] = tf32r(tb[j]);
        }
    };

    float acc[2][8][4] = {};
    loadA(0); loadB(0); stsA(0); stsB(0);
    __syncthreads();

    for (int c = 0; c < 16; c++) {
        if (c + 1 < 16) { loadA((c + 1) * 32); loadB((c + 1) * 32); }
        const int buf = c & 1;
        const float* Ab = As + buf * 128 * APAD;
        const float* Bb = Bs + buf * 32 * BPAD;

        #pragma unroll
        for (int ks = 0; ks < 4; ks++) {
            const int kk = ks * 8 + (lane & 3);
            uint32_t a[2][4], b[8][2];
            #pragma unroll
            for (int ma = 0; ma < 2; ma++) {
                int r = wm * 32 + ma * 16 + (lane >> 2);
                a[ma][0] = __float_as_uint(Ab[r * APAD + kk]);
                a[ma][1] = __float_as_uint(Ab[(r + 8) * APAD + kk]);
                a[ma][2] = __float_as_uint(Ab[r * APAD + kk + 4]);
                a[ma][3] = __float_as_uint(Ab[(r + 8) * APAD + kk + 4]);
            }
            #pragma unroll
            for (int na = 0; na < 8; na++) {
                int n = wn * 64 + na * 8 + (lane >> 2);
                b[na][0] = __float_as_uint(Bb[kk * BPAD + n]);
                b[na][1] = __float_as_uint(Bb[(kk + 4) * BPAD + n]);
            }
            #pragma unroll
            for (int ma = 0; ma < 2; ma++)
                #pragma unroll
                for (int na = 0; na < 8; na++)
                    mma8(acc[ma][na], a[ma], b[na]);
        }
        __syncthreads();
        if (c + 1 < 16) { stsA(buf ^ 1); stsB(buf ^ 1); }
        __syncthreads();
    }

    // epilogue: tf32-round + head-split scatter
    #pragma unroll
    for (int ma = 0; ma < 2; ma++) {
        #pragma unroll
        for (int half = 0; half < 2; half++) {
            int r = row0 + wm * 32 + ma * 16 + half * 8 + (lane >> 2);
            int bb = r >> 11, n = r & 2047;
            #pragma unroll
            for (int na = 0; na < 8; na++) {
                int cgl = col0 + wn * 64 + na * 8 + (lane & 3) * 2;
                int h = cgl >> 6, d = cgl & 63;
                float p = tf32r(acc[ma][na][half * 2 + 0]);
                float q = tf32r(acc[ma][na][half * 2 + 1]);
                long base = (long)(bb * H_ + h) * N_ + n;
                if (mode == 0)
                    *(float2*)&g_Q2[base * DQ2 + d] = make_float2(p, q);
                else if (mode == 1)
                    *(float2*)&g_Q2[base * DQ2 + d + DH] = make_float2(p, q);
                else if (mode == 2)
                    *(float2*)&g_K2[base * DQ2 + d] = make_float2(p, q);
                else if (mode == 3)
                    *(float2*)&g_K2[base * DQ2 + d + DH] = make_float2(p, q);
                else {
                    g_Vt[((long)(bb * H_ + h) * DH + d) * N_ + n] = p;
                    g_Vt[((long)(bb * H_ + h) * DH + d + 1) * N_ + n] = q;
                }
            }
        }
    }
}

// ===========================================================================
// Kernel 2: sim = (Q2 @ K2^T) * SCALE via mma.sync tf32.  (R3 verbatim)
// ===========================================================================
#define SIM_SMEM ((16384 + 2*4096) * 4)   // 98304 B

__global__ __launch_bounds__(256) void sim_tc(float* __restrict__ attn)
{
    extern __shared__ uint32_t sm[];
    uint32_t* Qs = sm;              // [qm4][ma2][ks16][lane32][4]
    uint32_t* Kb = sm + 16384;      // 2 x [wn2][na8][ks4][lane32][2]

    const int tid = threadIdx.x, lane = tid & 31, wid = tid >> 5;
    const int wm = wid >> 1, wn = wid & 1;
    const int bh = blockIdx.y, rb = blockIdx.x;
    const float* Qg = g_Q2 + ((long)bh * N_ + rb * 128) * DQ2;
    const float* Kg = g_K2 + (long)bh * N_ * DQ2;
    float* outp = attn + (long)bh * N_ * N_ + (long)rb * 128 * N_;

    for (int e = tid; e < 4096; e += 256) {
        int l = e & 31, ks = (e >> 5) & 15, ma = (e >> 9) & 1, qm = e >> 10;
        int r = qm * 32 + ma * 16 + (l >> 2), c = ks * 8 + (l & 3);
        uint4 v;
        v.x = __float_as_uint(Qg[(long)r * DQ2 + c]);
        v.y = __float_as_uint(Qg[(long)(r + 8) * DQ2 + c]);
        v.z = __float_as_uint(Qg[(long)r * DQ2 + c + 4]);
        v.w = __float_as_uint(Qg[(long)(r + 8) * DQ2 + c + 4]);
        *(uint4*)&Qs[e * 4] = v;
    }

    float4 tmp[4];
    auto loadK = [&](int it) {
        int ct = it >> 2, kc = it & 3;
        const float* src = Kg + (long)(ct * 128) * DQ2 + kc * 32;
        #pragma unroll
        for (int q = 0; q < 4; q++) {
            int e = tid + q * 256;
            int col = e >> 3, kg = e & 7;
            tmp[q] = *(const float4*)(src + (long)col * DQ2 + kg * 4);
        }
    };
    auto storeK = [&](int buf) {
        uint32_t* Bb = Kb + buf * 4096;
        #pragma unroll
        for (int q = 0; q < 4; q++) {
            int e = tid + q * 256;
            int col = e >> 3, kg = e & 7;
            int wn_ = col >> 6, na = (col >> 3) & 7;
            uint32_t vv[4] = { __float_as_uint(tmp[q].x), __float_as_uint(tmp[q].y),
                               __float_as_uint(tmp[q].z), __float_as_uint(tmp[q].w) };
            #pragma unroll
            for (int t = 0; t < 4; t++) {
                int k = kg * 4 + t;
                int l = ((col & 7) << 2) | (k & 3);
                Bb[((((wn_ * 8 + na) * 4 + (k >> 3)) * 32) + l) * 2 + ((k >> 2) & 1)] = vv[t];
            }
        }
    };

    float acc[2][8][4];
    loadK(0); storeK(0);
    __syncthreads();

    for (int it = 0; it < 64; it++) {
        const int kc = it & 3, buf = it & 1;
        if (kc == 0) {
            #pragma unroll
            for (int i = 0; i < 2; i++)
                #pragma unroll
                for (int j = 0; j < 8; j++)
                    #pragma unroll
                    for (int t = 0; t < 4; t++) acc[i][j][t] = 0.f;
        }
        if (it + 1 < 64) loadK(it + 1);

        const uint32_t* Bb = Kb + buf * 4096;
        #pragma unroll
        for (int ksl = 0; ksl < 4; ksl++) {
            int ksg = kc * 4 + ksl;
            uint32_t a[2][4], b[8][2];
            *(uint4*)a[0] = *(const uint4*)&Qs[(((wm * 2 + 0) * 16 + ksg) * 32 + lane) * 4];
            *(uint4*)a[1] = *(const uint4*)&Qs[(((wm * 2 + 1) * 16 + ksg) * 32 + lane) * 4];
            #pragma unroll
            for (int na = 0; na < 8; na++)
                *(uint2*)b[na] = *(const uint2*)&Bb[(((wn * 8 + na) * 4 + ksl) * 32 + lane) * 2];
            #pragma unroll
            for (int ma = 0; ma < 2; ma++)
                #pragma unroll
                for (int na = 0; na < 8; na++)
                    mma8(acc[ma][na], a[ma], b[na]);
        }

        if (kc == 3) {
            int ct = it >> 2;
            #pragma unroll
            for (int ma = 0; ma < 2; ma++) {
                int row = wm * 32 + ma * 16 + (lane >> 2);
                #pragma unroll
                for (int na = 0; na < 8; na++) {
                    int col = ct * 128 + wn * 64 + na * 8 + (lane & 3) * 2;
                    float2 lo = make_float2(acc[ma][na][0] * SCALE, acc[ma][na][1] * SCALE);
                    float2 hi = make_float2(acc[ma][na][2] * SCALE, acc[ma][na][3] * SCALE);
                    *(float2*)&outp[(long)row * N_ + col] = lo;
                    *(float2*)&outp[(long)(row + 8) * N_ + col] = hi;
                }
            }
        }
        if (it + 1 < 64) storeK(buf ^ 1);
        __syncthreads();
    }
}

// ===========================================================================
// Kernel 3: row softmax in place  (R3 verbatim)
// ===========================================================================
__global__ __launch_bounds__(256) void softmax_kernel(float* __restrict__ attn)
{
    float* p = attn + (long)blockIdx.x * N_;
    const int tid = threadIdx.x;

    float4 v0 = ((const float4*)p)[tid];
    float4 v1 = ((const float4*)p)[tid + 256];

    float m = fmaxf(fmaxf(fmaxf(v0.x, v0.y), fmaxf(v0.z, v0.w)),
                    fmaxf(fmaxf(v1.x, v1.y), fmaxf(v1.z, v1.w)));
    #pragma unroll
    for (int o = 16; o > 0; o >>= 1) m = fmaxf(m, __shfl_xor_sync(0xffffffffu, m, o));

    __shared__ float redm[8];
    if ((tid & 31) == 0) redm[tid >> 5] = m;
    __syncthreads();
    float mm = redm[0];
    #pragma unroll
    for (int i = 1; i < 8; i++) mm = fmaxf(mm, redm[i]);

    float4 e0, e1;
    e0.x = expf(v0.x - mm); e0.y = expf(v0.y - mm);
    e0.z = expf(v0.z - mm); e0.w = expf(v0.w - mm);
    e1.x = expf(v1.x - mm); e1.y = expf(v1.y - mm);
    e1.z = expf(v1.z - mm); e1.w = expf(v1.w - mm);

    float s = (e0.x + e0.y) + (e0.z + e0.w) + (e1.x + e1.y) + (e1.z + e1.w);
    #pragma unroll
    for (int o = 16; o > 0; o >>= 1) s += __shfl_xor_sync(0xffffffffu, s, o);

    __shared__ float reds[8];
    if ((tid & 31) == 0) reds[tid >> 5] = s;
    __syncthreads();
    float ss = 0.f;
    #pragma unroll
    for (int i = 0; i < 8; i++) ss += reds[i];

    float inv = 1.0f / ss;
    e0.x *= inv; e0.y *= inv; e0.z *= inv; e0.w *= inv;
    e1.x *= inv; e1.y *= inv; e1.z *= inv; e1.w *= inv;
    ((float4*)p)[tid]       = e0;
    ((float4*)p)[tid + 256] = e1;
}

// ===========================================================================
// Kernel 4: OutH = attn @ V via mma.sync tf32  (R3 verbatim)
// ===========================================================================
#define PV_SMEM ((2*4096 + 2*2048) * 4)   // 49152 B

__global__ __launch_bounds__(256) void pv_tc(const float* __restrict__ attn)
{
    extern __shared__ uint32_t sm[];
    uint32_t* Ab = sm;            // 2 x [wm4][ma2][ks4][lane32][4]
    uint32_t* Bv = sm + 8192;     // 2 x [wn2][na4][ks4][lane32][2]

    const int tid = threadIdx.x, lane = tid & 31, wid = tid >> 5;
    const int wm = wid >> 1, wn = wid & 1;
    const int bh = blockIdx.y, rb = blockIdx.x;
    const float* Ag = attn + (long)bh * N_ * N_ + (long)rb * 128 * N_;
    const float* Vg = g_Vt + (long)bh * DH * N_;

    float4 ta[4], tb[2];
    auto loadT = [&](int it) {
        #pragma unroll
        for (int q = 0; q < 4; q++) {
            int e = tid + q * 256;
            int row = e >> 3, kg = e & 7;
            ta[q] = *(const float4*)(Ag + (long)row * N_ + it * 32 + kg * 4);
        }
        #pragma unroll
        for (int q = 0; q < 2; q++) {
            int e = tid + q * 256;
            int d = e >> 3, kg = e & 7;
            tb[q] = *(const float4*)(Vg + (long)d * N_ + it * 32 + kg * 4);
        }
    };
    auto storeT = [&](int buf) {
        uint32_t* A = Ab + buf * 4096;
        #pragma unroll
        for (int q = 0; q < 4; q++) {
            int e = tid + q * 256;
            int row = e >> 3, kg = e & 7;
            int wm_ = row >> 5, ma = (row >> 4) & 1, rr = row & 15;
            float f[4] = { ta[q].x, ta[q].y, ta[q].z, ta[q].w };
            #pragma unroll
            for (int t = 0; t < 4; t++) {
                int k = kg * 4 + t;
                int j = ((k >> 2) & 1) * 2 + (rr >> 3);
                int l = ((rr & 7) << 2) | (k & 3);
                A[((((wm_ * 2 + ma) * 4 + (k >> 3)) * 32) + l) * 4 + j] =
                    __float_as_uint(tf32r(f[t]));
            }
        }
        uint32_t* Bt = Bv + buf * 2048;
        #pragma unroll
        for (int q = 0; q < 2; q++) {
            int e = tid + q * 256;
            int d = e >> 3, kg = e & 7;
            int wn_ = d >> 5, na = (d >> 3) & 3;
            float f[4] = { tb[q].x, tb[q].y, tb[q].z, tb[q].w };
            #pragma unroll
            for (int t = 0; t < 4; t++) {
                int k = kg * 4 + t;
                int l = ((d & 7) << 2) | (k & 3);
                Bt[((((wn_ * 4 + na) * 4 + (k >> 3)) * 32) + l) * 2 + ((k >> 2) & 1)] =
                    __float_as_uint(f[t]);
            }
        }
    };

    float acc[2][4][4] = {};
    loadT(0); storeT(0);
    __syncthreads();

    for (int it = 0; it < 64; it++) {
        const int buf = it & 1;
        if (it + 1 < 64) loadT(it + 1);

        const uint32_t* A = Ab + buf * 4096;
        const uint32_t* Bt = Bv + buf * 2048;
        #pragma unroll
        for (int ks = 0; ks < 4; ks++) {
            uint32_t a[2][4], b[4][2];
            *(uint4*)a[0] = *(const uint4*)&A[(((wm * 2 + 0) * 4 + ks) * 32 + lane) * 4];
            *(uint4*)a[1] = *(const uint4*)&A[(((wm * 2 + 1) * 4 + ks) * 32 + lane) * 4];
            #pragma unroll
            for (int na = 0; na < 4; na++)
                *(uint2*)b[na] = *(const uint2*)&Bt[(((wn * 4 + na) * 4 + ks) * 32 + lane) * 2];
            #pragma unroll
            for (int ma = 0; ma < 2; ma++)
                #pragma unroll
                for (int na = 0; na < 4; na++)
                    mma8(acc[ma][na], a[ma], b[na]);
        }
        if (it + 1 < 64) storeT(buf ^ 1);
        __syncthreads();
    }

    const int b = bh >> 3, h = bh & 7;
    float* oh = g_OH + ((long)b * N_ + rb * 128) * D_ + h * DH;
    #pragma unroll
    for (int ma = 0; ma < 2; ma++) {
        int row = wm * 32 + ma * 16 + (lane >> 2);
        #pragma unroll
        for (int na = 0; na < 4; na++) {
            int col = wn * 32 + na * 8 + (lane & 3) * 2;
            *(float2*)&oh[(long)row * D_ + col] =
                make_float2(acc[ma][na][0], acc[ma][na][1]);
            *(float2*)&oh[(long)(row + 8) * D_ + col] =
                make_float2(acc[ma][na][2], acc[ma][na][3]);
        }
    }
}

// ===========================================================================
// Kernel 5: Out = OutH @ Wo + bo via mma.sync tf32 (same scheme as proj_mma)
// ===========================================================================
__global__ __launch_bounds__(256) void outproj_mma(
    const float* __restrict__ Wo, const float* __restrict__ bo,
    float* __restrict__ out)
{
    extern __shared__ float smf[];
    float* As = smf;
    float* Bs = smf + 2*128*APAD;

    const int tid = threadIdx.x, lane = tid & 31, wid = tid >> 5;
    const int wm = wid >> 1, wn = wid & 1;
    const int row0 = blockIdx.y * 128;
    const int col0 = blockIdx.x * 128;

    float4 ta[4]; float tb[16];
    auto loadA = [&](int k0) {
        #pragma unroll
        for (int q = 0; q < 4; q++) {
            int e = tid + q * 256;
            int r = e >> 3, kg = e & 7;
            ta[q] = *(const float4*)&g_OH[(long)(row0 + r) * D_ + k0 + kg * 4];
        }
    };
    auto loadB = [&](int k0) {
        #pragma unroll
        for (int j = 0; j < 16; j++) {
            int i = tid + j * 256;
            int k = i >> 7, n = i & 127;
            tb[j] = Wo[(long)(k0 + k) * D_ + col0 + n];
        }
    };
    auto stsA = [&](int buf) {
        float* Ab = As + buf * 128 * APAD;
        #pragma unroll
        for (int q = 0; q < 4; q++) {
            int e = tid + q * 256;
            int r = e >> 3, kg = e & 7;
            float4 v = ta[q];
            v.x = tf32r(v.x); v.y = tf32r(v.y); v.z = tf32r(v.z); v.w = tf32r(v.w);
            *(float4*)&Ab[r * APAD + kg * 4] = v;
        }
    };
    auto stsB = [&](int buf) {
        float* Bb = Bs + buf * 32 * BPAD;
        #pragma unroll
        for (int j = 0; j < 16; j++) {
            int i = tid + j * 256;
            int k = i >> 7, n = i & 127;
            Bb[k * BPAD + n] = tf32r(tb[j]);
        }
    };

    float acc[2][8][4] = {};
    loadA(0); loadB(0); stsA(0); stsB(0);
    __syncthreads();

    for (int c = 0; c < 16; c++) {
        if (c + 1 < 16) { loadA((c + 1) * 32); loadB((c + 1) * 32); }
        const int buf = c & 1;
        const float* Ab = As + buf * 128 * APAD;
        const float* Bb = Bs + buf * 32 * BPAD;

        #pragma unroll
        for (int ks = 0; ks < 4; ks++) {
            const int kk = ks * 8 + (lane & 3);
            uint32_t a[2][4], b[8][2];
            #pragma unroll
            for (int ma = 0; ma < 2; ma++) {
                int r = wm * 32 + ma * 16 + (lane >> 2);
                a[ma][0] = __float_as_uint(Ab[r * APAD + kk]);
                a[ma][1] = __float_as_uint(Ab[(r + 8) * APAD + kk]);
                a[ma][2] = __float_as_uint(Ab[r * APAD + kk + 4]);
                a[ma][3] = __float_as_uint(Ab[(r + 8) * APAD + kk + 4]);
            }
            #pragma unroll
            for (int na = 0; na < 8; na++) {
                int n = wn * 64 + na * 8 + (lane >> 2);
                b[na][0] = __float_as_uint(Bb[kk * BPAD + n]);
                b[na][1] = __float_as_uint(Bb[(kk + 4) * BPAD + n]);
            }
            #pragma unroll
            for (int ma = 0; ma < 2; ma++)
                #pragma unroll
                for (int na = 0; na < 8; na++)
                    mma8(acc[ma][na], a[ma], b[na]);
        }
        __syncthreads();
        if (c + 1 < 16) { stsA(buf ^ 1); stsB(buf ^ 1); }
        __syncthreads();
    }

    #pragma unroll
    for (int ma = 0; ma < 2; ma++) {
        #pragma unroll
        for (int half = 0; half < 2; half++) {
            int r = row0 + wm * 32 + ma * 16 + half * 8 + (lane >> 2);
            #pragma unroll
            for (int na = 0; na < 8; na++) {
                int cgl = col0 + wn * 64 + na * 8 + (lane & 3) * 2;
                float2 bias = *(const float2*)&bo[cgl];
                *(float2*)&out[(long)r * D_ + cgl] =
                    make_float2(acc[ma][na][half * 2 + 0] + bias.x,
                                acc[ma][na][half * 2 + 1] + bias.y);
            }
        }
    }
}

// ===========================================================================
extern "C" void kernel_launch(void* const* d_in, const int* in_sizes, int n_in,
                              void* d_out, int out_size)
{
    (void)in_sizes; (void)n_in; (void)out_size;
    const float* x   = (const float*)d_in[0];
    const float* met = (const float*)d_in[1];
    const float* yz  = (const float*)d_in[2];
    const float* Wq  = (const float*)d_in[3];
    const float* Wk  = (const float*)d_in[4];
    const float* Wv  = (const float*)d_in[5];
    const float* Wo  = (const float*)d_in[6];
    const float* bo  = (const float*)d_in[7];

    float* out  = (float*)d_out;                       // (4, 2048, 512)
    float* attn = out + (long)B_ * N_ * D_;            // (32, 2048, 2048)

    static int configured = 0;
    if (!configured) {
        cudaFuncSetAttribute(proj_mma,    cudaFuncAttributeMaxDynamicSharedMemorySize, PROJ_SMEM);
        cudaFuncSetAttribute(sim_tc,      cudaFuncAttributeMaxDynamicSharedMemorySize, SIM_SMEM);
        cudaFuncSetAttribute(pv_tc,       cudaFuncAttributeMaxDynamicSharedMemorySize, PV_SMEM);
        cudaFuncSetAttribute(outproj_mma, cudaFuncAttributeMaxDynamicSharedMemorySize, PROJ_SMEM);
        configured = 1;
    }

    proj_mma      <<<dim3(4, 64, 5), 256, PROJ_SMEM>>>(x, met, yz, Wq, Wk, Wv);
    sim_tc        <<<dim3(16, 32), 256, SIM_SMEM>>>(attn);
    softmax_kernel<<<BHn * N_, 256>>>(attn);
    pv_tc         <<<dim3(16, 32), 256, PV_SMEM>>>(attn);
    outproj_mma   <<<dim3(4, 64), 256, PROJ_SMEM>>>(Wo, bo, out);
}